// round 5
// baseline (speedup 1.0000x reference)
#include <cuda_runtime.h>

#define BB 8
#define CC 64
#define WH 214272             // 496*432
#define WH4 53568             // WH/4
#define WH32 6696             // WH/32
#define BLOCKS_PER_BATCH 837  // WH / 256
#define NBLOCKS (BB * BLOCKS_PER_BATCH)
#define EPSF 0.001f

// Scratch (device globals — no allocations allowed).
// Zero-initialized at module load; the merged finalize tail resets them after
// consuming, so every graph replay starts from a clean state.
__device__ float        g_S1[CC];
__device__ float        g_S2[CC];
__device__ int          g_n[BB];
__device__ float        g_inv[CC];
__device__ unsigned int g_maskbits[BB * WH32];   // 1 bit per position, 214 KB
__device__ unsigned int g_done;

// ---------------------------------------------------------------------------
// Pass 1: per-channel sums + per-batch nonzero count + packed mask bitmap.
// Unmasked positions are exactly zero in every channel, so plain sums equal
// masked sums. The warp ballot (32 consecutive positions) IS the mask word.
// Last block to finish runs finalize inline.
// ---------------------------------------------------------------------------
__global__ void __launch_bounds__(256) stats_kernel(const float* __restrict__ x) {
    const int tid  = threadIdx.x;
    const int b    = blockIdx.x / BLOCKS_PER_BATCH;
    const int pos  = (blockIdx.x % BLOCKS_PER_BATCH) * 256 + tid;
    const float* xb = x + (size_t)b * CC * WH + pos;

    float v[CC];
    float csum = 0.0f;
#pragma unroll
    for (int c = 0; c < CC; c++) {
        v[c] = __ldcs(&xb[(size_t)c * WH]);   // streaming: no reuse before norm
        csum += v[c];
    }
    const bool m = (csum != 0.0f);

    const int warp = tid >> 5;
    const int lane = tid & 31;

    __shared__ float sm[128 * 65];   // 33.3 KB transpose buffer (padded)
    __shared__ float r1[256];
    __shared__ float r2[256];
    __shared__ int   sCnt[8];

    unsigned ballot = __ballot_sync(0xffffffffu, m);
    if (lane == 0) {
        sCnt[warp] = __popc(ballot);
        g_maskbits[b * WH32 + (pos >> 5)] = ballot;   // pos>>5 == block*8+warp
    }

    const int c = tid & 63;          // channel this thread reduces
    const int g = tid >> 6;          // position group (4 groups x 32 pos)
    float a1 = 0.0f, a2 = 0.0f;

#pragma unroll
    for (int phase = 0; phase < 2; phase++) {
        if ((tid >> 7) == phase) {
            const int row = tid & 127;
#pragma unroll
            for (int cc = 0; cc < CC; cc++) sm[row * 65 + cc] = v[cc];
        }
        __syncthreads();
#pragma unroll
        for (int i = 0; i < 32; i++) {
            float val = sm[(g * 32 + i) * 65 + c];
            a1 += val;
            a2 += val * val;
        }
        __syncthreads();
    }

    r1[tid] = a1;
    r2[tid] = a2;
    __syncthreads();

    if (tid < CC) {
        float s1 = r1[tid] + r1[tid + 64] + r1[tid + 128] + r1[tid + 192];
        float s2 = r2[tid] + r2[tid + 64] + r2[tid + 128] + r2[tid + 192];
        atomicAdd(&g_S1[tid], s1);
        atomicAdd(&g_S2[tid], s2);
    }
    if (tid == 0) {
        int cn = 0;
#pragma unroll
        for (int w = 0; w < 8; w++) cn += sCnt[w];
        atomicAdd(&g_n[b], cn);
    }

    // ---- merged finalize: last block computes inv + resets accumulators ----
    __shared__ bool isLast;
    __shared__ int  spad[BB];
    __shared__ int  sN;
    __threadfence();
    if (tid == 0) {
        unsigned int d = atomicAdd(&g_done, 1u);
        isLast = (d == (unsigned int)(NBLOCKS - 1));
    }
    __syncthreads();
    if (!isLast) return;

    if (tid == 0) {
        g_done = 0;
        int mx = 0;
#pragma unroll
        for (int bb = 0; bb < BB; bb++) mx = max(mx, g_n[bb]);
        sN = mx;
#pragma unroll
        for (int bb = 0; bb < BB; bb++) {
            spad[bb] = mx - g_n[bb];
            g_n[bb] = 0;
        }
    }
    __syncthreads();
    if (tid < CC) {
        float s1 = g_S1[tid];
        float s2 = g_S2[tid];
#pragma unroll
        for (int bb = 0; bb < BB; bb++) {
            float x00 = x[(size_t)bb * CC * WH + (size_t)tid * WH];
            float p = (float)spad[bb];
            s1 += p * x00;
            s2 += p * x00 * x00;
        }
        float count = (float)BB * (float)sN;
        float mean = s1 / count;
        float var  = s2 / count - mean * mean;
        g_inv[tid] = rsqrtf(var + EPSF);
        g_S1[tid] = 0.0f;
        g_S2[tid] = 0.0f;
    }
}

// ---------------------------------------------------------------------------
// Pass 2: normalize. out = x*inv[c] everywhere, but the x READ is predicated
// on the 4 mask bits: where all four positions are masked out, x is exactly
// zero -> write zeros without touching x. Cuts ~43% of the read sectors.
// ---------------------------------------------------------------------------
__global__ void __launch_bounds__(256) norm_kernel(const float* __restrict__ x,
                                                   float* __restrict__ out) {
    const unsigned int bc = blockIdx.y;       // b*64 + c  (0..511)
    const unsigned int b  = bc >> 6;
    const unsigned int c  = bc & 63u;
    const unsigned int p4 = blockIdx.x * 256u + threadIdx.x;
    if (p4 >= WH4) return;

    const unsigned int s  = p4 * 4u;          // position within plane
    const size_t i4 = (size_t)bc * WH4 + p4;

    const unsigned int word = g_maskbits[b * WH32 + (s >> 5)];
    const unsigned int nib  = (word >> (s & 31u)) & 0xFu;

    float4 o = make_float4(0.0f, 0.0f, 0.0f, 0.0f);
    if (nib) {
        const float inv = g_inv[c];
        float4 v = __ldcs(reinterpret_cast<const float4*>(x) + i4);
        o.x = v.x * inv;
        o.y = v.y * inv;
        o.z = v.z * inv;
        o.w = v.w * inv;
    }
    __stcs(reinterpret_cast<float4*>(out) + i4, o);
}

// ---------------------------------------------------------------------------
extern "C" void kernel_launch(void* const* d_in, const int* in_sizes, int n_in,
                              void* d_out, int out_size) {
    const float* x = (const float*)d_in[0];
    float* out = (float*)d_out;

    stats_kernel<<<NBLOCKS, 256>>>(x);
    dim3 ngrid((WH4 + 255) / 256, BB * CC);   // (210, 512)
    norm_kernel<<<ngrid, 256>>>(x, out);
}